// round 15
// baseline (speedup 1.0000x reference)
#include <cuda_runtime.h>
#include <cuda_fp16.h>
#include <cstdint>

// ---------------------------------------------------------------------------
// Problem constants
// ---------------------------------------------------------------------------
#define Bz   2
#define Cc   256
#define Oo   256
#define Ss   9216          // 96*96
#define CKk  2304          // 256*9
#define NCHUNK 36          // K chunks of 64; ck' = k*256 + c
#define NTILE  144         // 9216 / 64 pixels per GEMM tile

// Transposed input: [B][HW][C] fp16
__device__ __half g_inpT[(size_t)Bz * Ss * Cc];
// Packed weights: [chunk][256 rows x 64 fp16, SW128] = 32KB per chunk
__device__ __align__(1024) unsigned char g_wA[(size_t)NCHUNK * 32768];

// Bilinear tables (global, L1-resident per-SM working set):
//   g_crdI[(b*Ss+s)*9+k] = packed tap indices (i01, i23)
//   g_crdW[(b*Ss+s)*9+k] = 4 weights as duplicated half2
__device__ __align__(16) uint2 g_crdI[(size_t)Bz * Ss * 9];
__device__ __align__(16) uint4 g_crdW[(size_t)Bz * Ss * 9];

#define SWZ(o) ((o) ^ (((o) >> 3) & 0x70))

__device__ __forceinline__ uint32_t smem_u32(const void* p) {
    uint32_t a;
    asm("{ .reg .u64 t; cvta.to.shared.u64 t, %1; cvt.u32.u64 %0, t; }"
        : "=r"(a) : "l"(p));
    return a;
}
__device__ __forceinline__ __half2 h2_of(uint32_t u) {
    union { uint32_t u; __half2 h; } c; c.u = u; return c.h;
}

// ---- portable async-copy + tensor-core helpers ------------------------------
__device__ __forceinline__ void cp16(uint32_t dst, const void* src) {
    asm volatile("cp.async.cg.shared.global [%0], [%1], 16;"
                 :: "r"(dst), "l"(src) : "memory");
}
__device__ __forceinline__ void cp_commit() {
    asm volatile("cp.async.commit_group;" ::: "memory");
}
template <int N>
__device__ __forceinline__ void cp_wait() {
    asm volatile("cp.async.wait_group %0;" :: "n"(N) : "memory");
}
__device__ __forceinline__ void ldm4(uint32_t* r, uint32_t addr) {
    asm volatile("ldmatrix.sync.aligned.m8n8.x4.shared.b16 {%0,%1,%2,%3}, [%4];"
                 : "=r"(r[0]), "=r"(r[1]), "=r"(r[2]), "=r"(r[3]) : "r"(addr));
}
__device__ __forceinline__ void mma16816(float* d, const uint32_t* a,
                                         uint32_t b0, uint32_t b1) {
    asm volatile(
        "mma.sync.aligned.m16n8k16.row.col.f32.f16.f16.f32 "
        "{%0,%1,%2,%3}, {%4,%5,%6,%7}, {%8,%9}, {%0,%1,%2,%3};"
        : "+f"(d[0]), "+f"(d[1]), "+f"(d[2]), "+f"(d[3])
        : "r"(a[0]), "r"(a[1]), "r"(a[2]), "r"(a[3]), "r"(b0), "r"(b1));
}

// ---------------------------------------------------------------------------
// prep_k: ONE launch, three independent overlapped phases:
//   blocks [0, 2304)     : transpose input -> [B][HW][C] fp16
//   blocks [2304, 3456)  : pack weights -> fp16 SW128 tiles (ck' = k*256+c)
//   blocks [3456, 4104)  : precompute bilinear index/weight tables
// ---------------------------------------------------------------------------
__global__ __launch_bounds__(256) void prep_k(
    const float* __restrict__ inp,   // [B,256,96,96]
    const float* __restrict__ w,     // [256,256,3,3]
    const float* __restrict__ off,   // [B,18,96,96]
    const float* __restrict__ msk)   // [B,9,96,96]
{
    __shared__ float t[32][65];
    const int bx  = blockIdx.x;
    const int tid = threadIdx.x;

    if (bx < 2304) {
        // ---- transpose ----
        const int b  = bx / 1152;
        const int r  = bx - b * 1152;
        const int s0 = (r % 288) * 32;
        const int c0 = (r / 288) * 64;
        const int tx = tid & 31;
        const int ty = tid >> 5;
#pragma unroll
        for (int j = 0; j < 8; j++) {
            int cl = ty + j * 8;
            t[tx][cl] = inp[((size_t)(b * Cc + c0 + cl)) * Ss + s0 + tx];
        }
        __syncthreads();
#pragma unroll
        for (int j = 0; j < 4; j++) {
            int sl = ty + j * 8;
            __half2 h = __floats2half2_rn(t[sl][2 * tx], t[sl][2 * tx + 1]);
            *(__half2*)&g_inpT[((size_t)b * Ss + s0 + sl) * Cc + c0 + 2 * tx] = h;
        }
    } else if (bx < 3456) {
        // ---- weight pack ----
        int tt = (bx - 2304) * 256 + tid;
        int lane  = tt & 31;
        int row   = (tt >> 5) & 255;
        int chunk = tt >> 13;
        int k  = chunk >> 2;
        int c  = (chunk & 3) * 64 + 2 * lane;

        float wa = w[(size_t)row * CKk + c * 9 + k];
        float wb = w[(size_t)row * CKk + (c + 1) * 9 + k];

        unsigned char* base = g_wA + (size_t)chunk * 32768;
        int o = SWZ(row * 128 + lane * 4);
        *(__half2*)(base + o) = __floats2half2_rn(wa, wb);
    } else {
        // ---- bilinear coordinate/weight precompute ----
        int idx = (bx - 3456) * 256 + tid;     // (b*Ss + s)*9 + k
        int k   = idx % 9;
        int bs  = idx / 9;
        int s   = bs % Ss;
        int b   = bs / Ss;
        int oh = s / 96;
        int ow = s - oh * 96;

        float dy = off[((size_t)(b * 18 + 2 * k)) * Ss + s];
        float dx = off[((size_t)(b * 18 + 2 * k + 1)) * Ss + s];
        float m  = msk[((size_t)(b * 9 + k)) * Ss + s];

        float y = (float)(oh - 1 + k / 3) + dy;
        float x = (float)(ow - 1 + k % 3) + dx;
        float yf = floorf(y), xf = floorf(x);
        float wy = y - yf,    wx = x - xf;
        int iy = (int)yf, ix = (int)xf;

        float vy0 = (iy >= 0     && iy < 96)     ? 1.0f : 0.0f;
        float vy1 = (iy + 1 >= 0 && iy + 1 < 96) ? 1.0f : 0.0f;
        float vx0 = (ix >= 0     && ix < 96)     ? 1.0f : 0.0f;
        float vx1 = (ix + 1 >= 0 && ix + 1 < 96) ? 1.0f : 0.0f;
        int cy0 = min(max(iy, 0), 95),     cy1 = min(max(iy + 1, 0), 95);
        int cx0 = min(max(ix, 0), 95),     cx1 = min(max(ix + 1, 0), 95);

        float f00 = m * (1.0f - wy) * (1.0f - wx) * vy0 * vx0;
        float f01 = m * (1.0f - wy) * wx          * vy0 * vx1;
        float f10 = m * wy * (1.0f - wx)          * vy1 * vx0;
        float f11 = m * wy * wx                   * vy1 * vx1;

        union { __half2 h; uint32_t u; } u00, u01, u10, u11;
        u00.h = __float2half2_rn(f00);
        u01.h = __float2half2_rn(f01);
        u10.h = __float2half2_rn(f10);
        u11.h = __float2half2_rn(f11);

        uint2 ci;
        ci.x = (uint32_t)(cy0 * 96 + cx0) | ((uint32_t)(cy0 * 96 + cx1) << 16);
        ci.y = (uint32_t)(cy1 * 96 + cx0) | ((uint32_t)(cy1 * 96 + cx1) << 16);
        uint4 cw;
        cw.x = u00.u;  cw.y = u01.u;  cw.z = u10.u;  cw.w = u11.u;
        g_crdI[idx] = ci;
        g_crdW[idx] = cw;
    }
}

// ---------------------------------------------------------------------------
// Fused kernel: deformable-gather producer + fp16 mma.sync GEMM
// CTA: M=256, N=64 (64 px), 256 threads (8 warps), grid (144, 2) = 288 CTAs
// -> 2 CTAs per SM. Single-barrier pipeline: A 3-stage (refill issued at
// chunk start into the already-free stage, lands with a full chunk of slack),
// B 2-stage, Crd via L1-cached global loads. ONE __syncthreads per chunk.
// Smem per CTA: A 3x32K | B 2x8K = 112KB (2 CTAs = 224KB, fits)
// ---------------------------------------------------------------------------
#define SM_A     0
#define A_STAGE  32768
#define SM_B     98304
#define B_STAGE  8192
#define SMEM_TOTAL 114688

struct PTask { uint4 v00, v01, v10, v11; int px; };

__device__ __forceinline__ PTask prod_issue(const uint2* __restrict__ cI,
                                            const __half* __restrict__ bp,
                                            int px_base, int k, int lane) {
    PTask t;
    t.px = px_base + (lane >> 3);
    uint2 c = __ldg(&cI[t.px * 9 + k]);
    int i00 = c.x & 0xffff, i01 = c.x >> 16;
    int i10 = c.y & 0xffff, i11 = c.y >> 16;
    t.v00 = *(const uint4*)(bp + (size_t)i00 * Cc);
    t.v01 = *(const uint4*)(bp + (size_t)i01 * Cc);
    t.v10 = *(const uint4*)(bp + (size_t)i10 * Cc);
    t.v11 = *(const uint4*)(bp + (size_t)i11 * Cc);
    return t;
}

__device__ __forceinline__ void prod_complete(const uint4* __restrict__ cW,
                                              const PTask& t, int k, int lane,
                                              unsigned char* __restrict__ bh) {
    uint4 cw = __ldg(&cW[t.px * 9 + k]);
    __half2 w00 = h2_of(cw.x), w01 = h2_of(cw.y);
    __half2 w10 = h2_of(cw.z), w11 = h2_of(cw.w);
    union { uint4 u; __half2 h[4]; } x00, x01, x10, x11, pk;
    x00.u = t.v00; x01.u = t.v01; x10.u = t.v10; x11.u = t.v11;
#pragma unroll
    for (int j = 0; j < 4; j++) {
        __half2 r = __hmul2(x00.h[j], w00);
        r = __hfma2(x01.h[j], w01, r);
        r = __hfma2(x10.h[j], w10, r);
        r = __hfma2(x11.h[j], w11, r);
        pk.h[j] = r;
    }
    int sw = SWZ(t.px * 128 + (lane & 7) * 16);
    *(uint4*)(bh + sw) = pk.u;
}

__global__ __launch_bounds__(256, 2) void gemm_fused(
    const float* __restrict__ bias,
    float* __restrict__ out)
{
    extern __shared__ __align__(128) unsigned char smem[];
    const uint32_t sb = smem_u32(smem);

    const int tid  = threadIdx.x;
    const int wid  = tid >> 5;       // 0..7
    const int lane = tid & 31;
    const int n_t  = blockIdx.x;     // 0..143
    const int b    = blockIdx.y;

    const __half* inpT_b = g_inpT + (size_t)b * Ss * Cc;
    const uint2* cI = g_crdI + ((size_t)b * Ss + n_t * 64) * 9;
    const uint4* cW = g_crdW + ((size_t)b * Ss + n_t * 64) * 9;
    const int pxb = wid * 8;

    // ---- prologue: A(0), A(1) prefetch; B(0) production; chunk-1 issue ----
    {
        uint32_t st = sb + SM_A;
#pragma unroll
        for (int i = 0; i < 8; i++)
            cp16(st + (tid + i * 256) * 16, g_wA + (size_t)(tid + i * 256) * 16);
        cp_commit();                                  // g0: A0
#pragma unroll
        for (int i = 0; i < 8; i++)
            cp16(st + A_STAGE + (tid + i * 256) * 16,
                 g_wA + 32768 + (size_t)(tid + i * 256) * 16);
        cp_commit();                                  // g1: A1
    }
    {
        unsigned char* bdst = smem + SM_B;
        const __half* bp = inpT_b + (lane & 7) * 8;   // chunk 0: k=0, cg=0
#pragma unroll
        for (int e = 0; e < 2; e++) {
            PTask t = prod_issue(cI, bp, pxb + 4 * e, 0, lane);
            prod_complete(cW, t, 0, lane, bdst);
        }
    }
    PTask taP, tbP;
    {
        const __half* bp = inpT_b + 1 * 64 + (lane & 7) * 8;  // chunk 1
        taP = prod_issue(cI, bp, pxb + 0, 0, lane);
        tbP = prod_issue(cI, bp, pxb + 4, 0, lane);
    }
    cp_wait<1>();        // A0 complete (this thread)
    __syncthreads();     // A0 + B0 visible to all

    // per-warp MMA tile: 8 warps = 4(m) x 2(n); warp tile 64(m) x 32(n)
    const int wm = (wid & 3) * 64;
    const int wn = (wid >> 2) * 32;

    const int a_r  = (lane & 7) + ((lane >> 3) & 1) * 8;
    const int a_cb = (lane >> 4) * 16;
    const int b_r  = (lane & 7) + (lane >> 4) * 8;
    const int b_cb = ((lane >> 3) & 1) * 16;

    float acc[4][4][4];
#pragma unroll
    for (int i = 0; i < 4; i++)
#pragma unroll
        for (int j = 0; j < 4; j++)
#pragma unroll
            for (int q = 0; q < 4; q++) acc[i][j][q] = 0.0f;

    for (int ch = 0; ch < NCHUNK; ch++) {
        const uint32_t stA = sb + SM_A + (ch % 3) * A_STAGE;
        const uint32_t stB = sb + SM_B + (ch & 1) * B_STAGE;

        // A(ch+2) refill into the free stage, issued BEFORE compute:
        // that stage held A(ch-1), whose reads ended at the last barrier.
        if (ch + 2 < NCHUNK) {
            uint32_t stP = sb + SM_A + ((ch + 2) % 3) * A_STAGE;
            const unsigned char* a = g_wA + (size_t)(ch + 2) * 32768;
#pragma unroll
            for (int i = 0; i < 8; i++)
                cp16(stP + (tid + i * 256) * 16, a + (tid + i * 256) * 16);
        }
        cp_commit();       // uniform group accounting

        // producer: completes chunk ch+1 (issued last iter), issues ch+2
        const bool cmpl = (ch + 1 < NCHUNK);
        const bool issu = (ch + 2 < NCHUNK);
        const int k_c  = (ch + 1) >> 2;
        const int k_i  = (ch + 2) >> 2;
        unsigned char* bdst = smem + SM_B + ((ch + 1) & 1) * B_STAGE;
        const __half* bp_i = inpT_b + ((ch + 2) & 3) * 64 + (lane & 7) * 8;

#pragma unroll
        for (int ks = 0; ks < 4; ks++) {
            const int kb = ks * 32;

            uint32_t Bf[2][4];
#pragma unroll
            for (int np = 0; np < 2; np++) {
                int row = wn + np * 16 + b_r;
                uint32_t rel = row * 128 + ((kb + b_cb) ^ ((row & 7) * 16));
                ldm4(Bf[np], stB + rel);
            }

            // A-fragment software pipeline
            uint32_t Af[2][4];
            {
                int row = wm + a_r;
                uint32_t rel = row * 128 + ((kb + a_cb) ^ ((row & 7) * 16));
                ldm4(Af[0], stA + rel);
            }
#pragma unroll
            for (int mf = 0; mf < 4; mf++) {
                if (mf < 3) {
                    int row = wm + (mf + 1) * 16 + a_r;
                    uint32_t rel = row * 128 + ((kb + a_cb) ^ ((row & 7) * 16));
                    ldm4(Af[(mf + 1) & 1], stA + rel);
                }
#pragma unroll
                for (int nf = 0; nf < 4; nf++)
                    mma16816(acc[mf][nf], Af[mf & 1],
                             Bf[nf >> 1][(nf & 1) * 2],
                             Bf[nf >> 1][(nf & 1) * 2 + 1]);
            }

            if (ks == 0 && cmpl) prod_complete(cW, taP, k_c, lane, bdst);
            if (ks == 1 && cmpl) prod_complete(cW, tbP, k_c, lane, bdst);
            if (ks == 2 && issu) taP = prod_issue(cI, bp_i, pxb + 0, k_i, lane);
            if (ks == 3 && issu) tbP = prod_issue(cI, bp_i, pxb + 4, k_i, lane);
        }

        cp_wait<1>();      // A(ch+1) complete (committed last iteration)
        __syncthreads();   // A(ch+1) + B(ch+1) visible; A/B stage reads done
    }

    // ---- epilogue ----
    const int mrow = lane >> 2;
    const int ncol = (lane & 3) * 2;
#pragma unroll
    for (int mf = 0; mf < 4; mf++) {
        int m0 = wm + mf * 16 + mrow;
        float bv0 = __ldg(bias + m0);
        float bv8 = __ldg(bias + m0 + 8);
        float* r0 = out + ((size_t)(b * Oo + m0)) * Ss + n_t * 64;
        float* r8 = r0 + (size_t)8 * Ss;
#pragma unroll
        for (int nf = 0; nf < 4; nf++) {
            int n = wn + nf * 8 + ncol;
            float2 v0, v8;
            v0.x = acc[mf][nf][0] + bv0;  v0.y = acc[mf][nf][1] + bv0;
            v8.x = acc[mf][nf][2] + bv8;  v8.y = acc[mf][nf][3] + bv8;
            *(float2*)(r0 + n) = v0;
            *(float2*)(r8 + n) = v8;
        }
    }
}

// ---------------------------------------------------------------------------
extern "C" void kernel_launch(void* const* d_in, const int* in_sizes, int n_in,
                              void* d_out, int out_size)
{
    const float* inp  = (const float*)d_in[0];
    const float* off  = (const float*)d_in[1];
    const float* msk  = (const float*)d_in[2];
    const float* wt   = (const float*)d_in[3];
    const float* bias = (const float*)d_in[4];
    float* out = (float*)d_out;

    cudaFuncSetAttribute(gemm_fused, cudaFuncAttributeMaxDynamicSharedMemorySize,
                         SMEM_TOTAL);

    prep_k<<<4104, 256>>>(inp, wt, off, msk);   // transpose + wpack + crd
    {
        dim3 g(NTILE, Bz);                      // (144, 2) -> 288 CTAs, 2 per SM
        gemm_fused<<<g, 256, SMEM_TOTAL>>>(bias, out);
    }
}

// round 16
// speedup vs baseline: 1.1621x; 1.1621x over previous
#include <cuda_runtime.h>
#include <cuda_fp16.h>
#include <cstdint>

// ---------------------------------------------------------------------------
// Problem constants
// ---------------------------------------------------------------------------
#define Bz   2
#define Cc   256
#define Oo   256
#define Ss   9216          // 96*96
#define CKk  2304          // 256*9
#define NCHUNK 36          // K chunks of 64; ck' = k*256 + c
#define NTILE  144         // 9216 / 64 pixels per GEMM tile

// Transposed input: [B][HW][C] fp16
__device__ __half g_inpT[(size_t)Bz * Ss * Cc];
// Packed weights: [chunk][256 rows x 64 fp16, SW128] = 32KB per chunk
__device__ __align__(1024) unsigned char g_wA[(size_t)NCHUNK * 32768];

// Bilinear record: 4 packed tap indices + 4 weights as duplicated half2
struct __align__(8) Crd { uint32_t i01, i23, w00, w01, w10, w11; };
__device__ __align__(16) Crd g_crd[(size_t)Bz * Ss * 9];

#define SWZ(o) ((o) ^ (((o) >> 3) & 0x70))

__device__ __forceinline__ uint32_t smem_u32(const void* p) {
    uint32_t a;
    asm("{ .reg .u64 t; cvta.to.shared.u64 t, %1; cvt.u32.u64 %0, t; }"
        : "=r"(a) : "l"(p));
    return a;
}
__device__ __forceinline__ __half2 h2_of(uint32_t u) {
    union { uint32_t u; __half2 h; } c; c.u = u; return c.h;
}

// ---- portable async-copy + tensor-core helpers ------------------------------
__device__ __forceinline__ void cp16(uint32_t dst, const void* src) {
    asm volatile("cp.async.cg.shared.global [%0], [%1], 16;"
                 :: "r"(dst), "l"(src) : "memory");
}
__device__ __forceinline__ void cp_commit() {
    asm volatile("cp.async.commit_group;" ::: "memory");
}
template <int N>
__device__ __forceinline__ void cp_wait() {
    asm volatile("cp.async.wait_group %0;" :: "n"(N) : "memory");
}
__device__ __forceinline__ void ldm4(uint32_t* r, uint32_t addr) {
    asm volatile("ldmatrix.sync.aligned.m8n8.x4.shared.b16 {%0,%1,%2,%3}, [%4];"
                 : "=r"(r[0]), "=r"(r[1]), "=r"(r[2]), "=r"(r[3]) : "r"(addr));
}
__device__ __forceinline__ void mma16816(float* d, const uint32_t* a,
                                         uint32_t b0, uint32_t b1) {
    asm volatile(
        "mma.sync.aligned.m16n8k16.row.col.f32.f16.f16.f32 "
        "{%0,%1,%2,%3}, {%4,%5,%6,%7}, {%8,%9}, {%0,%1,%2,%3};"
        : "+f"(d[0]), "+f"(d[1]), "+f"(d[2]), "+f"(d[3])
        : "r"(a[0]), "r"(a[1]), "r"(a[2]), "r"(a[3]), "r"(b0), "r"(b1));
}

// ---------------------------------------------------------------------------
// prep_k: ONE launch, three independent overlapped phases:
//   blocks [0, 2304)     : transpose input -> [B][HW][C] fp16
//   blocks [2304, 3456)  : pack weights -> fp16 SW128 tiles (ck' = k*256+c)
//   blocks [3456, 4104)  : precompute bilinear Crd table (half2 weights)
// ---------------------------------------------------------------------------
__global__ __launch_bounds__(256) void prep_k(
    const float* __restrict__ inp,   // [B,256,96,96]
    const float* __restrict__ w,     // [256,256,3,3]
    const float* __restrict__ off,   // [B,18,96,96]
    const float* __restrict__ msk)   // [B,9,96,96]
{
    __shared__ float t[32][65];
    const int bx  = blockIdx.x;
    const int tid = threadIdx.x;

    if (bx < 2304) {
        // ---- transpose ----
        const int b  = bx / 1152;
        const int r  = bx - b * 1152;
        const int s0 = (r % 288) * 32;
        const int c0 = (r / 288) * 64;
        const int tx = tid & 31;
        const int ty = tid >> 5;
#pragma unroll
        for (int j = 0; j < 8; j++) {
            int cl = ty + j * 8;
            t[tx][cl] = inp[((size_t)(b * Cc + c0 + cl)) * Ss + s0 + tx];
        }
        __syncthreads();
#pragma unroll
        for (int j = 0; j < 4; j++) {
            int sl = ty + j * 8;
            __half2 h = __floats2half2_rn(t[sl][2 * tx], t[sl][2 * tx + 1]);
            *(__half2*)&g_inpT[((size_t)b * Ss + s0 + sl) * Cc + c0 + 2 * tx] = h;
        }
    } else if (bx < 3456) {
        // ---- weight pack ----
        int tt = (bx - 2304) * 256 + tid;
        int lane  = tt & 31;
        int row   = (tt >> 5) & 255;
        int chunk = tt >> 13;
        int k  = chunk >> 2;
        int c  = (chunk & 3) * 64 + 2 * lane;

        float wa = w[(size_t)row * CKk + c * 9 + k];
        float wb = w[(size_t)row * CKk + (c + 1) * 9 + k];

        unsigned char* base = g_wA + (size_t)chunk * 32768;
        int o = SWZ(row * 128 + lane * 4);
        *(__half2*)(base + o) = __floats2half2_rn(wa, wb);
    } else {
        // ---- bilinear coordinate/weight precompute (half2 weights) ----
        int idx = (bx - 3456) * 256 + tid;     // (b*Ss + s)*9 + k
        int k   = idx % 9;
        int bs  = idx / 9;
        int s   = bs % Ss;
        int b   = bs / Ss;
        int oh = s / 96;
        int ow = s - oh * 96;

        float dy = off[((size_t)(b * 18 + 2 * k)) * Ss + s];
        float dx = off[((size_t)(b * 18 + 2 * k + 1)) * Ss + s];
        float m  = msk[((size_t)(b * 9 + k)) * Ss + s];

        float y = (float)(oh - 1 + k / 3) + dy;
        float x = (float)(ow - 1 + k % 3) + dx;
        float yf = floorf(y), xf = floorf(x);
        float wy = y - yf,    wx = x - xf;
        int iy = (int)yf, ix = (int)xf;

        float vy0 = (iy >= 0     && iy < 96)     ? 1.0f : 0.0f;
        float vy1 = (iy + 1 >= 0 && iy + 1 < 96) ? 1.0f : 0.0f;
        float vx0 = (ix >= 0     && ix < 96)     ? 1.0f : 0.0f;
        float vx1 = (ix + 1 >= 0 && ix + 1 < 96) ? 1.0f : 0.0f;
        int cy0 = min(max(iy, 0), 95),     cy1 = min(max(iy + 1, 0), 95);
        int cx0 = min(max(ix, 0), 95),     cx1 = min(max(ix + 1, 0), 95);

        float f00 = m * (1.0f - wy) * (1.0f - wx) * vy0 * vx0;
        float f01 = m * (1.0f - wy) * wx          * vy0 * vx1;
        float f10 = m * wy * (1.0f - wx)          * vy1 * vx0;
        float f11 = m * wy * wx                   * vy1 * vx1;

        union { __half2 h; uint32_t u; } u00, u01, u10, u11;
        u00.h = __float2half2_rn(f00);
        u01.h = __float2half2_rn(f01);
        u10.h = __float2half2_rn(f10);
        u11.h = __float2half2_rn(f11);

        Crd c;
        c.i01 = (uint32_t)(cy0 * 96 + cx0) | ((uint32_t)(cy0 * 96 + cx1) << 16);
        c.i23 = (uint32_t)(cy1 * 96 + cx0) | ((uint32_t)(cy1 * 96 + cx1) << 16);
        c.w00 = u00.u;  c.w01 = u01.u;  c.w10 = u10.u;  c.w11 = u11.u;
        g_crd[idx] = c;
    }
}

// ---------------------------------------------------------------------------
// Fused kernel: deformable-gather producer + fp16 mma.sync GEMM
// CTA: M=256, N=64 (64 px), 256 threads (8 warps), grid (144, 2) = 288 CTAs
// -> 2 CTAs per SM. B 3-stage; gathers issued one chunk ahead. ONE barrier
// per chunk: cp_wait<0> retires A(ch+1) copies (committed a full chunk ago),
// the barrier publishes A(ch+1)+B(ch+1) and frees A(ch)'s stage, then the
// A(ch+2) refill is issued into that stage with a full chunk to land.
// Smem per CTA: A 2x32K | B 3x8K | crd 13.8K = 103.9KB (2 CTAs fit)
// ---------------------------------------------------------------------------
#define SM_A     0
#define A_STAGE  32768
#define SM_B     65536
#define B_STAGE  8192
#define SM_CRD   90112
#define SMEM_TOTAL 103936    // 90112 + 576*24

struct PTask { uint4 v00, v01, v10, v11; int px; };

__device__ __forceinline__ PTask prod_issue(const Crd* __restrict__ crd,
                                            const __half* __restrict__ bp,
                                            int px_base, int k, int lane) {
    PTask t;
    t.px = px_base + (lane >> 3);
    Crd c = crd[t.px * 9 + k];
    int i00 = c.i01 & 0xffff, i01 = c.i01 >> 16;
    int i10 = c.i23 & 0xffff, i11 = c.i23 >> 16;
    t.v00 = *(const uint4*)(bp + (size_t)i00 * Cc);
    t.v01 = *(const uint4*)(bp + (size_t)i01 * Cc);
    t.v10 = *(const uint4*)(bp + (size_t)i10 * Cc);
    t.v11 = *(const uint4*)(bp + (size_t)i11 * Cc);
    return t;
}

__device__ __forceinline__ void prod_complete(const Crd* __restrict__ crd,
                                              const PTask& t, int k, int lane,
                                              unsigned char* __restrict__ bh) {
    Crd c = crd[t.px * 9 + k];
    __half2 w00 = h2_of(c.w00), w01 = h2_of(c.w01);
    __half2 w10 = h2_of(c.w10), w11 = h2_of(c.w11);
    union { uint4 u; __half2 h[4]; } x00, x01, x10, x11, pk;
    x00.u = t.v00; x01.u = t.v01; x10.u = t.v10; x11.u = t.v11;
#pragma unroll
    for (int j = 0; j < 4; j++) {
        __half2 r = __hmul2(x00.h[j], w00);
        r = __hfma2(x01.h[j], w01, r);
        r = __hfma2(x10.h[j], w10, r);
        r = __hfma2(x11.h[j], w11, r);
        pk.h[j] = r;
    }
    int sw = SWZ(t.px * 128 + (lane & 7) * 16);
    *(uint4*)(bh + sw) = pk.u;
}

__global__ __launch_bounds__(256, 2) void gemm_fused(
    const float* __restrict__ bias,
    float* __restrict__ out)
{
    extern __shared__ __align__(128) unsigned char smem[];
    const uint32_t sb = smem_u32(smem);

    const int tid  = threadIdx.x;
    const int wid  = tid >> 5;       // 0..7
    const int lane = tid & 31;
    const int n_t  = blockIdx.x;     // 0..143
    const int b    = blockIdx.y;

    Crd* crd = (Crd*)(smem + SM_CRD);
    const __half* inpT_b = g_inpT + (size_t)b * Ss * Cc;
    const int pxb = wid * 8;

    // ---- prologue: crd tile + A(0) in group 0; A(1) in group 1 ----
    {
        const unsigned char* gc =
            (const unsigned char*)(g_crd + ((size_t)b * Ss + n_t * 64) * 9);
        for (int i = tid; i < 864; i += 256)         // 13824 B
            cp16(sb + SM_CRD + i * 16, gc + i * 16);
        uint32_t st = sb + SM_A;
#pragma unroll
        for (int i = 0; i < 8; i++)
            cp16(st + (tid + i * 256) * 16, g_wA + (size_t)(tid + i * 256) * 16);
        cp_commit();                                  // g0: crd + A0
#pragma unroll
        for (int i = 0; i < 8; i++)
            cp16(st + A_STAGE + (tid + i * 256) * 16,
                 g_wA + 32768 + (size_t)(tid + i * 256) * 16);
        cp_commit();                                  // g1: A1
    }
    cp_wait<1>();        // crd + A0 complete (this thread)
    __syncthreads();     // crd + A0 visible to all

    // produce B chunk 0 into stage 0; issue gathers for chunk 1
    {
        unsigned char* bdst = smem + SM_B;
        const __half* bp = inpT_b + (lane & 7) * 8;   // chunk 0: k=0, cg=0
#pragma unroll
        for (int e = 0; e < 2; e++) {
            PTask t = prod_issue(crd, bp, pxb + 4 * e, 0, lane);
            prod_complete(crd, t, 0, lane, bdst);
        }
    }
    PTask taP, tbP;
    {
        const __half* bp = inpT_b + 1 * 64 + (lane & 7) * 8;  // chunk 1
        taP = prod_issue(crd, bp, pxb + 0, 0, lane);
        tbP = prod_issue(crd, bp, pxb + 4, 0, lane);
    }
    __syncthreads();     // B(0) sealed

    // per-warp MMA tile: 8 warps = 4(m) x 2(n); warp tile 64(m) x 32(n)
    const int wm = (wid & 3) * 64;
    const int wn = (wid >> 2) * 32;

    const int a_r  = (lane & 7) + ((lane >> 3) & 1) * 8;
    const int a_cb = (lane >> 4) * 16;
    const int b_r  = (lane & 7) + (lane >> 4) * 8;
    const int b_cb = ((lane >> 3) & 1) * 16;

    float acc[4][4][4];
#pragma unroll
    for (int i = 0; i < 4; i++)
#pragma unroll
        for (int j = 0; j < 4; j++)
#pragma unroll
            for (int q = 0; q < 4; q++) acc[i][j][q] = 0.0f;

    for (int ch = 0; ch < NCHUNK; ch++) {
        const uint32_t stA = sb + SM_A + (ch & 1) * A_STAGE;
        const uint32_t stB = sb + SM_B + (ch % 3) * B_STAGE;

        // completes chunk ch+1 (tasks issued last iteration);
        // issues chunk ch+2 (completed next iteration)
        const bool cmpl = (ch + 1 < NCHUNK);
        const bool issu = (ch + 2 < NCHUNK);
        const int k_c  = (ch + 1) >> 2;
        const int k_i  = (ch + 2) >> 2;
        unsigned char* bdst = smem + SM_B + ((ch + 1) % 3) * B_STAGE;
        const __half* bp_i = inpT_b + ((ch + 2) & 3) * 64 + (lane & 7) * 8;

#pragma unroll
        for (int ks = 0; ks < 4; ks++) {
            const int kb = ks * 32;

            uint32_t Bf[2][4];
#pragma unroll
            for (int np = 0; np < 2; np++) {
                int row = wn + np * 16 + b_r;
                uint32_t rel = row * 128 + ((kb + b_cb) ^ ((row & 7) * 16));
                ldm4(Bf[np], stB + rel);
            }

            // A-fragment software pipeline: frag for mf+1 loads while mf MMAs
            uint32_t Af[2][4];
            {
                int row = wm + a_r;
                uint32_t rel = row * 128 + ((kb + a_cb) ^ ((row & 7) * 16));
                ldm4(Af[0], stA + rel);
            }
#pragma unroll
            for (int mf = 0; mf < 4; mf++) {
                if (mf < 3) {
                    int row = wm + (mf + 1) * 16 + a_r;
                    uint32_t rel = row * 128 + ((kb + a_cb) ^ ((row & 7) * 16));
                    ldm4(Af[(mf + 1) & 1], stA + rel);
                }
#pragma unroll
                for (int nf = 0; nf < 4; nf++)
                    mma16816(acc[mf][nf], Af[mf & 1],
                             Bf[nf >> 1][(nf & 1) * 2],
                             Bf[nf >> 1][(nf & 1) * 2 + 1]);
            }

            if (ks == 0 && cmpl) prod_complete(crd, taP, k_c, lane, bdst);
            if (ks == 1 && cmpl) prod_complete(crd, tbP, k_c, lane, bdst);
            if (ks == 2 && issu) taP = prod_issue(crd, bp_i, pxb + 0, k_i, lane);
            if (ks == 3 && issu) tbP = prod_issue(crd, bp_i, pxb + 4, k_i, lane);
        }

        // ---- single-barrier tail ----
        cp_wait<0>();      // A(ch+1) copies complete (committed a chunk ago)
        __syncthreads();   // A(ch) reads done; A(ch+1) + B(ch+1) visible
        if (ch + 2 < NCHUNK) {
            // refill the A stage just retired (stage ch&1) with A(ch+2);
            // completion enforced by next iteration's cp_wait<0> + barrier
            const unsigned char* a = g_wA + (size_t)(ch + 2) * 32768;
#pragma unroll
            for (int i = 0; i < 8; i++)
                cp16(stA + (tid + i * 256) * 16, a + (tid + i * 256) * 16);
        }
        cp_commit();       // uniform group accounting (empty groups fine)
    }

    // ---- epilogue ----
    const int mrow = lane >> 2;
    const int ncol = (lane & 3) * 2;
#pragma unroll
    for (int mf = 0; mf < 4; mf++) {
        int m0 = wm + mf * 16 + mrow;
        float bv0 = __ldg(bias + m0);
        float bv8 = __ldg(bias + m0 + 8);
        float* r0 = out + ((size_t)(b * Oo + m0)) * Ss + n_t * 64;
        float* r8 = r0 + (size_t)8 * Ss;
#pragma unroll
        for (int nf = 0; nf < 4; nf++) {
            int n = wn + nf * 8 + ncol;
            float2 v0, v8;
            v0.x = acc[mf][nf][0] + bv0;  v0.y = acc[mf][nf][1] + bv0;
            v8.x = acc[mf][nf][2] + bv8;  v8.y = acc[mf][nf][3] + bv8;
            *(float2*)(r0 + n) = v0;
            *(float2*)(r8 + n) = v8;
        }
    }
}

// ---------------------------------------------------------------------------
extern "C" void kernel_launch(void* const* d_in, const int* in_sizes, int n_in,
                              void* d_out, int out_size)
{
    const float* inp  = (const float*)d_in[0];
    const float* off  = (const float*)d_in[1];
    const float* msk  = (const float*)d_in[2];
    const float* wt   = (const float*)d_in[3];
    const float* bias = (const float*)d_in[4];
    float* out = (float*)d_out;

    cudaFuncSetAttribute(gemm_fused, cudaFuncAttributeMaxDynamicSharedMemorySize,
                         SMEM_TOTAL);

    prep_k<<<4104, 256>>>(inp, wt, off, msk);   // transpose + wpack + crd
    {
        dim3 g(NTILE, Bz);                      // (144, 2) -> 288 CTAs, 2 per SM
        gemm_fused<<<g, 256, SMEM_TOTAL>>>(bias, out);
    }
}

// round 17
// speedup vs baseline: 1.2157x; 1.0462x over previous
#include <cuda_runtime.h>
#include <cuda_fp16.h>
#include <cstdint>

// ---------------------------------------------------------------------------
// Problem constants
// ---------------------------------------------------------------------------
#define Bz   2
#define Cc   256
#define Oo   256
#define Ss   9216          // 96*96
#define CKk  2304          // 256*9
#define NCHUNK 36          // K chunks of 64; ck' = k*256 + c
#define NTILE  144         // 9216 / 64 pixels per GEMM tile

// Transposed input: [B][HW][C] fp16
__device__ __half g_inpT[(size_t)Bz * Ss * Cc];
// Packed weights: [chunk][256 rows x 64 fp16, SW128] = 32KB per chunk
__device__ __align__(1024) unsigned char g_wA[(size_t)NCHUNK * 32768];

// Bilinear record: 4 packed tap indices + 4 weights as duplicated half2
struct __align__(8) Crd { uint32_t i01, i23, w00, w01, w10, w11; };
__device__ __align__(16) Crd g_crd[(size_t)Bz * Ss * 9];

#define SWZ(o) ((o) ^ (((o) >> 3) & 0x70))

__device__ __forceinline__ uint32_t smem_u32(const void* p) {
    uint32_t a;
    asm("{ .reg .u64 t; cvta.to.shared.u64 t, %1; cvt.u32.u64 %0, t; }"
        : "=r"(a) : "l"(p));
    return a;
}
__device__ __forceinline__ __half2 h2_of(uint32_t u) {
    union { uint32_t u; __half2 h; } c; c.u = u; return c.h;
}

// ---- portable async-copy + tensor-core helpers ------------------------------
__device__ __forceinline__ void cp16(uint32_t dst, const void* src) {
    asm volatile("cp.async.cg.shared.global [%0], [%1], 16;"
                 :: "r"(dst), "l"(src) : "memory");
}
__device__ __forceinline__ void cp_commit() {
    asm volatile("cp.async.commit_group;" ::: "memory");
}
template <int N>
__device__ __forceinline__ void cp_wait() {
    asm volatile("cp.async.wait_group %0;" :: "n"(N) : "memory");
}
__device__ __forceinline__ void ldm4(uint32_t* r, uint32_t addr) {
    asm volatile("ldmatrix.sync.aligned.m8n8.x4.shared.b16 {%0,%1,%2,%3}, [%4];"
                 : "=r"(r[0]), "=r"(r[1]), "=r"(r[2]), "=r"(r[3]) : "r"(addr));
}
__device__ __forceinline__ void mma16816(float* d, const uint32_t* a,
                                         uint32_t b0, uint32_t b1) {
    asm volatile(
        "mma.sync.aligned.m16n8k16.row.col.f32.f16.f16.f32 "
        "{%0,%1,%2,%3}, {%4,%5,%6,%7}, {%8,%9}, {%0,%1,%2,%3};"
        : "+f"(d[0]), "+f"(d[1]), "+f"(d[2]), "+f"(d[3])
        : "r"(a[0]), "r"(a[1]), "r"(a[2]), "r"(a[3]), "r"(b0), "r"(b1));
}

// ---------------------------------------------------------------------------
// prep_k: ONE launch, three independent overlapped phases:
//   blocks [0, 2304)     : transpose input -> [B][HW][C] fp16
//   blocks [2304, 3456)  : pack weights -> fp16 SW128 tiles (ck' = k*256+c)
//   blocks [3456, 4104)  : precompute bilinear Crd table (half2 weights)
// ---------------------------------------------------------------------------
__global__ __launch_bounds__(256) void prep_k(
    const float* __restrict__ inp,   // [B,256,96,96]
    const float* __restrict__ w,     // [256,256,3,3]
    const float* __restrict__ off,   // [B,18,96,96]
    const float* __restrict__ msk)   // [B,9,96,96]
{
    __shared__ float t[32][65];
    const int bx  = blockIdx.x;
    const int tid = threadIdx.x;

    if (bx < 2304) {
        // ---- transpose ----
        const int b  = bx / 1152;
        const int r  = bx - b * 1152;
        const int s0 = (r % 288) * 32;
        const int c0 = (r / 288) * 64;
        const int tx = tid & 31;
        const int ty = tid >> 5;
#pragma unroll
        for (int j = 0; j < 8; j++) {
            int cl = ty + j * 8;
            t[tx][cl] = inp[((size_t)(b * Cc + c0 + cl)) * Ss + s0 + tx];
        }
        __syncthreads();
#pragma unroll
        for (int j = 0; j < 4; j++) {
            int sl = ty + j * 8;
            __half2 h = __floats2half2_rn(t[sl][2 * tx], t[sl][2 * tx + 1]);
            *(__half2*)&g_inpT[((size_t)b * Ss + s0 + sl) * Cc + c0 + 2 * tx] = h;
        }
    } else if (bx < 3456) {
        // ---- weight pack ----
        int tt = (bx - 2304) * 256 + tid;
        int lane  = tt & 31;
        int row   = (tt >> 5) & 255;
        int chunk = tt >> 13;
        int k  = chunk >> 2;
        int c  = (chunk & 3) * 64 + 2 * lane;

        float wa = w[(size_t)row * CKk + c * 9 + k];
        float wb = w[(size_t)row * CKk + (c + 1) * 9 + k];

        unsigned char* base = g_wA + (size_t)chunk * 32768;
        int o = SWZ(row * 128 + lane * 4);
        *(__half2*)(base + o) = __floats2half2_rn(wa, wb);
    } else {
        // ---- bilinear coordinate/weight precompute (half2 weights) ----
        int idx = (bx - 3456) * 256 + tid;     // (b*Ss + s)*9 + k
        int k   = idx % 9;
        int bs  = idx / 9;
        int s   = bs % Ss;
        int b   = bs / Ss;
        int oh = s / 96;
        int ow = s - oh * 96;

        float dy = off[((size_t)(b * 18 + 2 * k)) * Ss + s];
        float dx = off[((size_t)(b * 18 + 2 * k + 1)) * Ss + s];
        float m  = msk[((size_t)(b * 9 + k)) * Ss + s];

        float y = (float)(oh - 1 + k / 3) + dy;
        float x = (float)(ow - 1 + k % 3) + dx;
        float yf = floorf(y), xf = floorf(x);
        float wy = y - yf,    wx = x - xf;
        int iy = (int)yf, ix = (int)xf;

        float vy0 = (iy >= 0     && iy < 96)     ? 1.0f : 0.0f;
        float vy1 = (iy + 1 >= 0 && iy + 1 < 96) ? 1.0f : 0.0f;
        float vx0 = (ix >= 0     && ix < 96)     ? 1.0f : 0.0f;
        float vx1 = (ix + 1 >= 0 && ix + 1 < 96) ? 1.0f : 0.0f;
        int cy0 = min(max(iy, 0), 95),     cy1 = min(max(iy + 1, 0), 95);
        int cx0 = min(max(ix, 0), 95),     cx1 = min(max(ix + 1, 0), 95);

        float f00 = m * (1.0f - wy) * (1.0f - wx) * vy0 * vx0;
        float f01 = m * (1.0f - wy) * wx          * vy0 * vx1;
        float f10 = m * wy * (1.0f - wx)          * vy1 * vx0;
        float f11 = m * wy * wx                   * vy1 * vx1;

        union { __half2 h; uint32_t u; } u00, u01, u10, u11;
        u00.h = __float2half2_rn(f00);
        u01.h = __float2half2_rn(f01);
        u10.h = __float2half2_rn(f10);
        u11.h = __float2half2_rn(f11);

        Crd c;
        c.i01 = (uint32_t)(cy0 * 96 + cx0) | ((uint32_t)(cy0 * 96 + cx1) << 16);
        c.i23 = (uint32_t)(cy1 * 96 + cx0) | ((uint32_t)(cy1 * 96 + cx1) << 16);
        c.w00 = u00.u;  c.w01 = u01.u;  c.w10 = u10.u;  c.w11 = u11.u;
        g_crd[idx] = c;
    }
}

// ---------------------------------------------------------------------------
// Fused kernel: deformable-gather producer + fp16 mma.sync GEMM
// CTA: M=256, N=64 (64 px), 256 threads (8 warps), grid (144, 2) = 288 CTAs
// -> 2 CTAs per SM. Single barrier per chunk (R16 scheme). NEW: B-fragment
// double-buffer across k-slices + cross-slice Af[0] prefetch, so ks1..ks3
// start with operands already in flight; producer shrunk to ONE in-flight
// PTask (complete t0@ks0 -> issue t1 -> complete t1@ks2 -> issue next t0).
// Smem per CTA: A 2x32K | B 3x8K | crd 13.8K = 103.9KB (2 CTAs fit)
// ---------------------------------------------------------------------------
#define SM_A     0
#define A_STAGE  32768
#define SM_B     65536
#define B_STAGE  8192
#define SM_CRD   90112
#define SMEM_TOTAL 103936    // 90112 + 576*24

struct PTask { uint4 v00, v01, v10, v11; int px; };

__device__ __forceinline__ PTask prod_issue(const Crd* __restrict__ crd,
                                            const __half* __restrict__ bp,
                                            int px_base, int k, int lane) {
    PTask t;
    t.px = px_base + (lane >> 3);
    Crd c = crd[t.px * 9 + k];
    int i00 = c.i01 & 0xffff, i01 = c.i01 >> 16;
    int i10 = c.i23 & 0xffff, i11 = c.i23 >> 16;
    t.v00 = *(const uint4*)(bp + (size_t)i00 * Cc);
    t.v01 = *(const uint4*)(bp + (size_t)i01 * Cc);
    t.v10 = *(const uint4*)(bp + (size_t)i10 * Cc);
    t.v11 = *(const uint4*)(bp + (size_t)i11 * Cc);
    return t;
}

__device__ __forceinline__ void prod_complete(const Crd* __restrict__ crd,
                                              const PTask& t, int k, int lane,
                                              unsigned char* __restrict__ bh) {
    Crd c = crd[t.px * 9 + k];
    __half2 w00 = h2_of(c.w00), w01 = h2_of(c.w01);
    __half2 w10 = h2_of(c.w10), w11 = h2_of(c.w11);
    union { uint4 u; __half2 h[4]; } x00, x01, x10, x11, pk;
    x00.u = t.v00; x01.u = t.v01; x10.u = t.v10; x11.u = t.v11;
#pragma unroll
    for (int j = 0; j < 4; j++) {
        __half2 r = __hmul2(x00.h[j], w00);
        r = __hfma2(x01.h[j], w01, r);
        r = __hfma2(x10.h[j], w10, r);
        r = __hfma2(x11.h[j], w11, r);
        pk.h[j] = r;
    }
    int sw = SWZ(t.px * 128 + (lane & 7) * 16);
    *(uint4*)(bh + sw) = pk.u;
}

__global__ __launch_bounds__(256, 2) void gemm_fused(
    const float* __restrict__ bias,
    float* __restrict__ out)
{
    extern __shared__ __align__(128) unsigned char smem[];
    const uint32_t sb = smem_u32(smem);

    const int tid  = threadIdx.x;
    const int wid  = tid >> 5;       // 0..7
    const int lane = tid & 31;
    const int n_t  = blockIdx.x;     // 0..143
    const int b    = blockIdx.y;

    Crd* crd = (Crd*)(smem + SM_CRD);
    const __half* inpT_b = g_inpT + (size_t)b * Ss * Cc;
    const int pxb = wid * 8;

    // ---- prologue: crd tile + A(0) in group 0; A(1) in group 1 ----
    {
        const unsigned char* gc =
            (const unsigned char*)(g_crd + ((size_t)b * Ss + n_t * 64) * 9);
        for (int i = tid; i < 864; i += 256)         // 13824 B
            cp16(sb + SM_CRD + i * 16, gc + i * 16);
        uint32_t st = sb + SM_A;
#pragma unroll
        for (int i = 0; i < 8; i++)
            cp16(st + (tid + i * 256) * 16, g_wA + (size_t)(tid + i * 256) * 16);
        cp_commit();                                  // g0: crd + A0
#pragma unroll
        for (int i = 0; i < 8; i++)
            cp16(st + A_STAGE + (tid + i * 256) * 16,
                 g_wA + 32768 + (size_t)(tid + i * 256) * 16);
        cp_commit();                                  // g1: A1
    }
    cp_wait<1>();        // crd + A0 complete (this thread)
    __syncthreads();     // crd + A0 visible to all

    // produce B chunk 0 into stage 0; issue gather for chunk 1 task 0
    {
        unsigned char* bdst = smem + SM_B;
        const __half* bp = inpT_b + (lane & 7) * 8;   // chunk 0: k=0, cg=0
#pragma unroll
        for (int e = 0; e < 2; e++) {
            PTask t = prod_issue(crd, bp, pxb + 4 * e, 0, lane);
            prod_complete(crd, t, 0, lane, bdst);
        }
    }
    PTask taP;
    {
        const __half* bp = inpT_b + 1 * 64 + (lane & 7) * 8;  // chunk 1
        taP = prod_issue(crd, bp, pxb + 0, 0, lane);
    }
    __syncthreads();     // B(0) sealed

    // per-warp MMA tile: 8 warps = 4(m) x 2(n); warp tile 64(m) x 32(n)
    const int wm = (wid & 3) * 64;
    const int wn = (wid >> 2) * 32;

    const int a_r  = (lane & 7) + ((lane >> 3) & 1) * 8;
    const int a_cb = (lane >> 4) * 16;
    const int b_r  = (lane & 7) + (lane >> 4) * 8;
    const int b_cb = ((lane >> 3) & 1) * 16;

    // precomputed per-warp fragment address bases (swizzle-resolved per row)
    const int bRow0 = wn + b_r;              // np=0 B row
    const int bRow1 = wn + 16 + b_r;         // np=1 B row

    float acc[4][4][4];
#pragma unroll
    for (int i = 0; i < 4; i++)
#pragma unroll
        for (int j = 0; j < 4; j++)
#pragma unroll
            for (int q = 0; q < 4; q++) acc[i][j][q] = 0.0f;

    for (int ch = 0; ch < NCHUNK; ch++) {
        const uint32_t stA = sb + SM_A + (ch & 1) * A_STAGE;
        const uint32_t stB = sb + SM_B + (ch % 3) * B_STAGE;

        const bool cmpl = (ch + 1 < NCHUNK);
        const bool issu = (ch + 2 < NCHUNK);
        const int k_c  = (ch + 1) >> 2;
        const int k_i  = (ch + 2) >> 2;
        unsigned char* bdst = smem + SM_B + ((ch + 1) % 3) * B_STAGE;
        const __half* bp_c = inpT_b + ((ch + 1) & 3) * 64 + (lane & 7) * 8;
        const __half* bp_i = inpT_b + ((ch + 2) & 3) * 64 + (lane & 7) * 8;

        // ---- initial fragment loads for ks0 (only exposed LDS point) ----
        uint32_t Bf[2][2][4];     // [ks&1][np][4]
        uint32_t Af[2][4];
        {
            uint32_t rel0 = bRow0 * 128 + ((b_cb) ^ ((bRow0 & 7) * 16));
            uint32_t rel1 = bRow1 * 128 + ((b_cb) ^ ((bRow1 & 7) * 16));
            ldm4(Bf[0][0], stB + rel0);
            ldm4(Bf[0][1], stB + rel1);
            int row = wm + a_r;
            ldm4(Af[0], stA + row * 128 + ((a_cb) ^ ((row & 7) * 16)));
        }

#pragma unroll
        for (int ks = 0; ks < 4; ks++) {
            const int kb = ks * 32;
            const int kbn = kb + 32;      // next slice's byte offset
            uint32_t (*Bc)[4] = Bf[ks & 1];
            uint32_t (*Bn)[4] = Bf[(ks + 1) & 1];

#pragma unroll
            for (int mf = 0; mf < 4; mf++) {
                if (mf < 3) {
                    int row = wm + (mf + 1) * 16 + a_r;
                    uint32_t rel = row * 128 + ((kb + a_cb) ^ ((row & 7) * 16));
                    ldm4(Af[(mf + 1) & 1], stA + rel);
                } else if (ks < 3) {
                    // cross-slice Af[0] prefetch (mf=3 uses Af[1]; slot free)
                    int row = wm + a_r;
                    uint32_t rel = row * 128 + ((kbn + a_cb) ^ ((row & 7) * 16));
                    ldm4(Af[0], stA + rel);
                }
                if (mf == 1 && ks < 3) {
                    // cross-slice B-fragment prefetch
                    uint32_t rel0 = bRow0 * 128 + ((kbn + b_cb) ^ ((bRow0 & 7) * 16));
                    uint32_t rel1 = bRow1 * 128 + ((kbn + b_cb) ^ ((bRow1 & 7) * 16));
                    ldm4(Bn[0], stB + rel0);
                    ldm4(Bn[1], stB + rel1);
                }
#pragma unroll
                for (int nf = 0; nf < 4; nf++)
                    mma16816(acc[mf][nf], Af[mf & 1],
                             Bc[nf >> 1][(nf & 1) * 2],
                             Bc[nf >> 1][(nf & 1) * 2 + 1]);
            }

            // single-slot producer schedule
            if (ks == 0 && cmpl) { prod_complete(crd, taP, k_c, lane, bdst);
                                   taP = prod_issue(crd, bp_c, pxb + 4, k_c, lane); }
            if (ks == 2 && cmpl) { prod_complete(crd, taP, k_c, lane, bdst);
                                   if (issu) taP = prod_issue(crd, bp_i, pxb + 0, k_i, lane); }
        }

        // ---- single-barrier tail ----
        cp_wait<0>();      // A(ch+1) copies complete (committed a chunk ago)
        __syncthreads();   // A(ch) reads done; A(ch+1) + B(ch+1) visible
        if (ch + 2 < NCHUNK) {
            const unsigned char* a = g_wA + (size_t)(ch + 2) * 32768;
#pragma unroll
            for (int i = 0; i < 8; i++)
                cp16(stA + (tid + i * 256) * 16, a + (tid + i * 256) * 16);
        }
        cp_commit();       // uniform group accounting (empty groups fine)
    }

    // ---- epilogue ----
    const int mrow = lane >> 2;
    const int ncol = (lane & 3) * 2;
#pragma unroll
    for (int mf = 0; mf < 4; mf++) {
        int m0 = wm + mf * 16 + mrow;
        float bv0 = __ldg(bias + m0);
        float bv8 = __ldg(bias + m0 + 8);
        float* r0 = out + ((size_t)(b * Oo + m0)) * Ss + n_t * 64;
        float* r8 = r0 + (size_t)8 * Ss;
#pragma unroll
        for (int nf = 0; nf < 4; nf++) {
            int n = wn + nf * 8 + ncol;
            float2 v0, v8;
            v0.x = acc[mf][nf][0] + bv0;  v0.y = acc[mf][nf][1] + bv0;
            v8.x = acc[mf][nf][2] + bv8;  v8.y = acc[mf][nf][3] + bv8;
            *(float2*)(r0 + n) = v0;
            *(float2*)(r8 + n) = v8;
        }
    }
}

// ---------------------------------------------------------------------------
extern "C" void kernel_launch(void* const* d_in, const int* in_sizes, int n_in,
                              void* d_out, int out_size)
{
    const float* inp  = (const float*)d_in[0];
    const float* off  = (const float*)d_in[1];
    const float* msk  = (const float*)d_in[2];
    const float* wt   = (const float*)d_in[3];
    const float* bias = (const float*)d_in[4];
    float* out = (float*)d_out;

    cudaFuncSetAttribute(gemm_fused, cudaFuncAttributeMaxDynamicSharedMemorySize,
                         SMEM_TOTAL);

    prep_k<<<4104, 256>>>(inp, wt, off, msk);   // transpose + wpack + crd
    {
        dim3 g(NTILE, Bz);                      // (144, 2) -> 288 CTAs, 2 per SM
        gemm_fused<<<g, 256, SMEM_TOTAL>>>(bias, out);
    }
}